// round 13
// baseline (speedup 1.0000x reference)
#include <cuda_runtime.h>
#include <cuda_fp16.h>
#include <cstdint>

// Problem constants (fixed by the dataset)
#define NN        100000
#define NE        3200000
#define INC       512
#define HID       256
#define OUTC      64
#define NBLK_SCAN 98      // ceil(NN / 1024)

// ---------------- scratch (static __device__ — no allocations) ----------------
__device__ float   g_hidden[(size_t)NN * HID];     // 102.4 MB
__device__ float   g_h0[(size_t)NN * OUTC];        // 25.6 MB (fp32 residual, final iter)
__device__ __half2 g_h0r16[(size_t)NN * (OUTC/2)]; // fp16 residual (iters 1-9)
__device__ __half2 g_h016[(size_t)NN * (OUTC/2)];  // prescaled fp16 (dinv*h)
__device__ __half2 g_hA16[(size_t)NN * (OUTC/2)];
__device__ __half2 g_hB16[(size_t)NN * (OUTC/2)];
__device__ int     g_cnt[NN];
__device__ int     g_rowptr[NN + 1];
__device__ int     g_fillpos[NN];
__device__ float   g_dinv[NN];
__device__ int     g_esrc[NE];                     // src only, 12.8 MB
__device__ int     g_bsums[NBLK_SCAN];

// ---------------- graph preprocessing ----------------
__global__ void k_zero_cnt() {
    int i = blockIdx.x * blockDim.x + threadIdx.x;
    if (i < NN) g_cnt[i] = 0;
}

// ei is int32 (JAX default x64-disabled downgrades int64 -> int32)
__global__ void k_count(const int* __restrict__ ei) {
    int e = blockIdx.x * blockDim.x + threadIdx.x;
    if (e < NE) {
        int d = ei[NE + e];
        if (d >= 0 && d < NN) atomicAdd(&g_cnt[d], 1);
    }
}

__global__ void k_dinv() {
    int i = blockIdx.x * blockDim.x + threadIdx.x;
    if (i < NN) g_dinv[i] = rsqrtf((float)(g_cnt[i] + 1)); // +1 self loop
}

__global__ void k_scan1() {
    __shared__ int s[1024];
    int tid = threadIdx.x;
    int i = blockIdx.x * 1024 + tid;
    int v = (i < NN) ? g_cnt[i] : 0;
    s[tid] = v;
    __syncthreads();
    for (int off = 1; off < 1024; off <<= 1) {
        int t = (tid >= off) ? s[tid - off] : 0;
        __syncthreads();
        s[tid] += t;
        __syncthreads();
    }
    if (i < NN) g_rowptr[i] = s[tid];
    if (tid == 1023) g_bsums[blockIdx.x] = s[1023];
}

__global__ void k_scan2() {
    if (threadIdx.x == 0) {
        int run = 0;
        for (int b = 0; b < NBLK_SCAN; b++) { int t = g_bsums[b]; g_bsums[b] = run; run += t; }
    }
}

__global__ void k_scan3() {
    int i = blockIdx.x * blockDim.x + threadIdx.x;
    if (i < NN) {
        int ex = g_rowptr[i] - g_cnt[i] + g_bsums[i >> 10]; // global exclusive
        g_rowptr[i]  = ex;
        g_fillpos[i] = ex;
    }
    if (i == 0) g_rowptr[NN] = NE;
}

__global__ void k_fill(const int* __restrict__ ei) {
    int e = blockIdx.x * blockDim.x + threadIdx.x;
    if (e < NE) {
        int s = ei[e];
        int d = ei[NE + e];
        if (s >= 0 && s < NN && d >= 0 && d < NN) {
            int p = atomicAdd(&g_fillpos[d], 1);
            g_esrc[p] = s;
        }
    }
}

// ---------------- tf32 helpers ----------------
__device__ __forceinline__ uint32_t f2tf(float f) {
    uint32_t u;
    asm("cvt.rna.tf32.f32 %0, %1;" : "=r"(u) : "f"(f));
    return u;
}

// ---------------- tf32 tensor-core GEMM1: C = relu(A @ B + bias) --------------
// 128x128 tile, BK=16, 8 warps (4m x 2n), warp tile 32x64, mma.m16n8k8 tf32
__global__ void __launch_bounds__(256) k_gemm1_tf32(
    const float* __restrict__ A, const float* __restrict__ B,
    const float* __restrict__ bias, int M, int N, int K)
{
    float* C = (float*)g_hidden;
    __shared__ uint32_t As[2][128][20];
    __shared__ uint32_t Bs[2][16][136];

    int tid = threadIdx.x;
    int lane = tid & 31, wid = tid >> 5;
    int wm = wid & 3, wn = wid >> 2;
    int g = lane >> 2, t = lane & 3;
    int row0 = blockIdx.x * 128, col0 = blockIdx.y * 128;

    int ar0 = tid >> 2;
    int ac  = (tid & 3) << 2;
    int br0 = tid >> 5;
    int bc  = (tid & 31) << 2;

    const float* Ap0 = A + (size_t)(row0 + ar0) * K + ac;
    const float* Ap1 = A + (size_t)(row0 + ar0 + 64) * K + ac;
    bool aok0 = (row0 + ar0) < M;
    bool aok1 = (row0 + ar0 + 64) < M;
    const float* Bp0 = B + (size_t)br0 * N + col0 + bc;
    const float* Bp1 = B + (size_t)(br0 + 8) * N + col0 + bc;

    float c[2][8][4] = {};

    const float4 fz = make_float4(0.f, 0.f, 0.f, 0.f);
    float4 av0 = aok0 ? *(const float4*)Ap0 : fz;
    float4 av1 = aok1 ? *(const float4*)Ap1 : fz;
    float4 bv0 = *(const float4*)Bp0;
    float4 bv1 = *(const float4*)Bp1;

    int nk = K >> 4;
    for (int kt = 0; kt < nk; kt++) {
        int cur = kt & 1;
        *(uint4*)&As[cur][ar0][ac]      = make_uint4(f2tf(av0.x), f2tf(av0.y), f2tf(av0.z), f2tf(av0.w));
        *(uint4*)&As[cur][ar0 + 64][ac] = make_uint4(f2tf(av1.x), f2tf(av1.y), f2tf(av1.z), f2tf(av1.w));
        *(uint4*)&Bs[cur][br0][bc]      = make_uint4(f2tf(bv0.x), f2tf(bv0.y), f2tf(bv0.z), f2tf(bv0.w));
        *(uint4*)&Bs[cur][br0 + 8][bc]  = make_uint4(f2tf(bv1.x), f2tf(bv1.y), f2tf(bv1.z), f2tf(bv1.w));
        __syncthreads();

        if (kt + 1 < nk) {
            int ko = (kt + 1) << 4;
            av0 = aok0 ? *(const float4*)(Ap0 + ko) : fz;
            av1 = aok1 ? *(const float4*)(Ap1 + ko) : fz;
            bv0 = *(const float4*)(Bp0 + (size_t)ko * N);
            bv1 = *(const float4*)(Bp1 + (size_t)ko * N);
        }

#pragma unroll
        for (int ks = 0; ks < 2; ks++) {
            int k = ks << 3;
            uint32_t af[2][4];
#pragma unroll
            for (int mi = 0; mi < 2; mi++) {
                int m0 = wm * 32 + mi * 16;
                af[mi][0] = As[cur][m0 + g][k + t];
                af[mi][1] = As[cur][m0 + g + 8][k + t];
                af[mi][2] = As[cur][m0 + g][k + t + 4];
                af[mi][3] = As[cur][m0 + g + 8][k + t + 4];
            }
            uint32_t bf[8][2];
#pragma unroll
            for (int ni = 0; ni < 8; ni++) {
                int n0 = wn * 64 + ni * 8;
                bf[ni][0] = Bs[cur][k + t][n0 + g];
                bf[ni][1] = Bs[cur][k + t + 4][n0 + g];
            }
#pragma unroll
            for (int mi = 0; mi < 2; mi++)
#pragma unroll
                for (int ni = 0; ni < 8; ni++) {
                    asm volatile(
                        "mma.sync.aligned.m16n8k8.row.col.f32.tf32.tf32.f32 "
                        "{%0,%1,%2,%3}, {%4,%5,%6,%7}, {%8,%9}, {%0,%1,%2,%3};"
                        : "+f"(c[mi][ni][0]), "+f"(c[mi][ni][1]),
                          "+f"(c[mi][ni][2]), "+f"(c[mi][ni][3])
                        : "r"(af[mi][0]), "r"(af[mi][1]), "r"(af[mi][2]), "r"(af[mi][3]),
                          "r"(bf[ni][0]), "r"(bf[ni][1]));
                }
        }
        __syncthreads();
    }

#pragma unroll
    for (int mi = 0; mi < 2; mi++) {
        int r = row0 + wm * 32 + mi * 16 + g;
#pragma unroll
        for (int ni = 0; ni < 8; ni++) {
            int cn = col0 + wn * 64 + ni * 8 + (t << 1);
            float2 bb = *(const float2*)&bias[cn];
            if (r < M) {
                float2 o;
                o.x = fmaxf(c[mi][ni][0] + bb.x, 0.f);
                o.y = fmaxf(c[mi][ni][1] + bb.y, 0.f);
                *(float2*)&C[(size_t)r * N + cn] = o;
            }
            if (r + 8 < M) {
                float2 o;
                o.x = fmaxf(c[mi][ni][2] + bb.x, 0.f);
                o.y = fmaxf(c[mi][ni][3] + bb.y, 0.f);
                *(float2*)&C[(size_t)(r + 8) * N + cn] = o;
            }
        }
    }
}

// ---------------- tf32 tensor-core GEMM2 (+fused prescale epilogue) ------------
// g_h0 = g_hidden @ W2 + b2 ; also emits g_h0r16 (fp16 h0) and g_h016 (fp16 dinv*h0)
// 128x64 tile, BK=16, 8 warps (4m x 2n), warp tile 32x32
__global__ void __launch_bounds__(256) k_gemm2_tf32(
    const float* __restrict__ B, const float* __restrict__ bias,
    int M, int N, int K)
{
    const float* A = (const float*)g_hidden;
    float* C = (float*)g_h0;
    __shared__ uint32_t As[2][128][20];
    __shared__ uint32_t Bs[2][16][72];

    int tid = threadIdx.x;
    int lane = tid & 31, wid = tid >> 5;
    int wm = wid & 3, wn = wid >> 2;
    int g = lane >> 2, t = lane & 3;
    int row0 = blockIdx.x * 128;

    int ar0 = tid >> 2;
    int ac  = (tid & 3) << 2;
    int br0 = tid >> 4;
    int bc  = (tid & 15) << 2;

    const float* Ap0 = A + (size_t)(row0 + ar0) * K + ac;
    const float* Ap1 = A + (size_t)(row0 + ar0 + 64) * K + ac;
    bool aok0 = (row0 + ar0) < M;
    bool aok1 = (row0 + ar0 + 64) < M;
    const float* Bp = B + (size_t)br0 * N + bc;

    float c[2][4][4] = {};

    const float4 fz = make_float4(0.f, 0.f, 0.f, 0.f);
    float4 av0 = aok0 ? *(const float4*)Ap0 : fz;
    float4 av1 = aok1 ? *(const float4*)Ap1 : fz;
    float4 bv = *(const float4*)Bp;

    int nk = K >> 4;
    for (int kt = 0; kt < nk; kt++) {
        int cur = kt & 1;
        *(uint4*)&As[cur][ar0][ac]      = make_uint4(f2tf(av0.x), f2tf(av0.y), f2tf(av0.z), f2tf(av0.w));
        *(uint4*)&As[cur][ar0 + 64][ac] = make_uint4(f2tf(av1.x), f2tf(av1.y), f2tf(av1.z), f2tf(av1.w));
        *(uint4*)&Bs[cur][br0][bc]      = make_uint4(f2tf(bv.x), f2tf(bv.y), f2tf(bv.z), f2tf(bv.w));
        __syncthreads();

        if (kt + 1 < nk) {
            int ko = (kt + 1) << 4;
            av0 = aok0 ? *(const float4*)(Ap0 + ko) : fz;
            av1 = aok1 ? *(const float4*)(Ap1 + ko) : fz;
            bv = *(const float4*)(Bp + (size_t)ko * N);
        }

#pragma unroll
        for (int ks = 0; ks < 2; ks++) {
            int k = ks << 3;
            uint32_t af[2][4];
#pragma unroll
            for (int mi = 0; mi < 2; mi++) {
                int m0 = wm * 32 + mi * 16;
                af[mi][0] = As[cur][m0 + g][k + t];
                af[mi][1] = As[cur][m0 + g + 8][k + t];
                af[mi][2] = As[cur][m0 + g][k + t + 4];
                af[mi][3] = As[cur][m0 + g + 8][k + t + 4];
            }
            uint32_t bf[4][2];
#pragma unroll
            for (int ni = 0; ni < 4; ni++) {
                int n0 = wn * 32 + ni * 8;
                bf[ni][0] = Bs[cur][k + t][n0 + g];
                bf[ni][1] = Bs[cur][k + t + 4][n0 + g];
            }
#pragma unroll
            for (int mi = 0; mi < 2; mi++)
#pragma unroll
                for (int ni = 0; ni < 4; ni++) {
                    asm volatile(
                        "mma.sync.aligned.m16n8k8.row.col.f32.tf32.tf32.f32 "
                        "{%0,%1,%2,%3}, {%4,%5,%6,%7}, {%8,%9}, {%0,%1,%2,%3};"
                        : "+f"(c[mi][ni][0]), "+f"(c[mi][ni][1]),
                          "+f"(c[mi][ni][2]), "+f"(c[mi][ni][3])
                        : "r"(af[mi][0]), "r"(af[mi][1]), "r"(af[mi][2]), "r"(af[mi][3]),
                          "r"(bf[ni][0]), "r"(bf[ni][1]));
                }
        }
        __syncthreads();
    }

#pragma unroll
    for (int mi = 0; mi < 2; mi++) {
        int r0 = row0 + wm * 32 + mi * 16 + g;
        float dv0 = (r0 < M) ? g_dinv[r0] : 0.f;
        float dv1 = (r0 + 8 < M) ? g_dinv[r0 + 8] : 0.f;
#pragma unroll
        for (int ni = 0; ni < 4; ni++) {
            int cn = wn * 32 + ni * 8 + (t << 1);
            float2 bb = *(const float2*)&bias[cn];
            if (r0 < M) {
                float2 o;
                o.x = c[mi][ni][0] + bb.x;
                o.y = c[mi][ni][1] + bb.y;
                *(float2*)&C[(size_t)r0 * N + cn] = o;
                size_t hi = (size_t)r0 * (OUTC / 2) + (cn >> 1);
                g_h0r16[hi] = __floats2half2_rn(o.x, o.y);
                g_h016[hi]  = __floats2half2_rn(dv0 * o.x, dv0 * o.y);
            }
            if (r0 + 8 < M) {
                float2 o;
                o.x = c[mi][ni][2] + bb.x;
                o.y = c[mi][ni][3] + bb.y;
                *(float2*)&C[(size_t)(r0 + 8) * N + cn] = o;
                size_t hi = (size_t)(r0 + 8) * (OUTC / 2) + (cn >> 1);
                g_h0r16[hi] = __floats2half2_rn(o.x, o.y);
                g_h016[hi]  = __floats2half2_rn(dv1 * o.x, dv1 * o.y);
            }
        }
    }
}

// ---------------- propagation ----------------
// gather buffers hold hs = dinv * h (prescaled). Per node d:
//   agg = dinv_d * ( sum_{in-edges} hs[s] + hs[d] )
//   h_next = 0.9*agg + 0.1*h0;  store dinv_d*h_next (fp16) or h_next (fp32 final)
// warp/node; half-warps process one edge each per step; lane (sub,c) covers
// cols 4c..4c+3. Full 32-edge blocks accumulate in fp16 (HADD2), promoted to
// fp32 per block; remainder edges accumulate in fp32.
__global__ void __launch_bounds__(256) k_prop(int src_id, int dst_id,
                                              float* __restrict__ ext_out)
{
    const __half2* hin = (src_id == 0) ? (const __half2*)g_h016
                       : (src_id == 1) ? (const __half2*)g_hA16
                                       : (const __half2*)g_hB16;
    __half2* hout16 = (dst_id == 1) ? (__half2*)g_hA16
                    : (dst_id == 2) ? (__half2*)g_hB16
                                    : nullptr;

    int node = (blockIdx.x * blockDim.x + threadIdx.x) >> 5;
    int lane = threadIdx.x & 31;
    if (node >= NN) return;
    int sub = lane >> 4;
    int c   = lane & 15;
    int beg = g_rowptr[node];
    int end = g_rowptr[node + 1];
    int deg = end - beg;
    int nfull = deg & ~31;

    float a0 = 0.f, a1 = 0.f, a2 = 0.f, a3 = 0.f;

    // full 32-edge blocks: fp16 accumulation, no predication
    for (int base = beg; base < beg + nfull; base += 32) {
        int es = g_esrc[base + lane];
        __half2 h01 = __float2half2_rn(0.f);
        __half2 h23 = __float2half2_rn(0.f);
#pragma unroll
        for (int j = 0; j < 16; j++) {
            int s = __shfl_sync(0xffffffffu, es, (j << 1) + sub);
            uint2 raw = *(const uint2*)(hin + (size_t)s * (OUTC / 2) + (c << 1));
            h01 = __hadd2(h01, *(__half2*)&raw.x);
            h23 = __hadd2(h23, *(__half2*)&raw.y);
        }
        float2 f0 = __half22float2(h01);
        float2 f1 = __half22float2(h23);
        a0 += f0.x; a1 += f0.y; a2 += f1.x; a3 += f1.y;
    }

    // remainder (<32 edges): fp32 accumulation with predication
    int rbeg = beg + nfull;
    int nb = end - rbeg;
    if (nb > 0) {
        int es = 0;
        if (lane < nb) es = g_esrc[rbeg + lane];
#pragma unroll 4
        for (int j = 0; j < 16; j++) {
            int e = (j << 1) + sub;
            int s = __shfl_sync(0xffffffffu, es, e);
            if (e < nb) {
                uint2 raw = *(const uint2*)(hin + (size_t)s * (OUTC / 2) + (c << 1));
                float2 f0 = __half22float2(*(__half2*)&raw.x);
                float2 f1 = __half22float2(*(__half2*)&raw.y);
                a0 += f0.x; a1 += f0.y; a2 += f1.x; a3 += f1.y;
            }
            if ((j << 1) + 2 >= nb) break;
        }
    }

    // merge the two half-warp partial sums
    a0 += __shfl_xor_sync(0xffffffffu, a0, 16);
    a1 += __shfl_xor_sync(0xffffffffu, a1, 16);
    a2 += __shfl_xor_sync(0xffffffffu, a2, 16);
    a3 += __shfl_xor_sync(0xffffffffu, a3, 16);

    if (sub == 0) {
        float dv = g_dinv[node];
        // self loop (prescaled row)
        uint2 sraw = *(const uint2*)(hin + (size_t)node * (OUTC / 2) + (c << 1));
        float2 s0 = __half22float2(*(__half2*)&sraw.x);
        float2 s1 = __half22float2(*(__half2*)&sraw.y);
        a0 += s0.x; a1 += s0.y; a2 += s1.x; a3 += s1.y;

        if (hout16) {
            // residual from fp16 h0 copy
            uint2 rraw = *(const uint2*)(g_h0r16 + (size_t)node * (OUTC / 2) + (c << 1));
            float2 r0 = __half22float2(*(__half2*)&rraw.x);
            float2 r1 = __half22float2(*(__half2*)&rraw.y);
            float o0 = 0.9f * dv * a0 + 0.1f * r0.x;
            float o1 = 0.9f * dv * a1 + 0.1f * r0.y;
            float o2 = 0.9f * dv * a2 + 0.1f * r1.x;
            float o3 = 0.9f * dv * a3 + 0.1f * r1.y;
            __half2* op = hout16 + (size_t)node * (OUTC / 2) + (c << 1);
            uint2 ow;
            *(__half2*)&ow.x = __floats2half2_rn(dv * o0, dv * o1);
            *(__half2*)&ow.y = __floats2half2_rn(dv * o2, dv * o3);
            *(uint2*)op = ow;
        } else {
            // final iteration: fp32 residual, fp32 output
            float4 h0v = *(const float4*)(g_h0 + (size_t)node * OUTC + (c << 2));
            float o0 = 0.9f * dv * a0 + 0.1f * h0v.x;
            float o1 = 0.9f * dv * a1 + 0.1f * h0v.y;
            float o2 = 0.9f * dv * a2 + 0.1f * h0v.z;
            float o3 = 0.9f * dv * a3 + 0.1f * h0v.w;
            *(float4*)(ext_out + (size_t)node * OUTC + (c << 2)) =
                make_float4(o0, o1, o2, o3);
        }
    }
}

// ---------------- launch ----------------
extern "C" void kernel_launch(void* const* d_in, const int* in_sizes, int n_in,
                              void* d_out, int out_size)
{
    const float* x  = (const float*)d_in[0];
    const int*   ei = (const int*)d_in[1];     // int32 (JAX x64 disabled)
    const float* W1 = (const float*)d_in[2];
    const float* b1 = (const float*)d_in[3];
    const float* W2 = (const float*)d_in[4];
    const float* b2 = (const float*)d_in[5];
    float* out = (float*)d_out;

    static cudaStream_t s2 = nullptr;
    static cudaEvent_t evFork = nullptr, evJoin = nullptr;
    if (s2 == nullptr) {
        cudaStreamCreateWithFlags(&s2, cudaStreamNonBlocking);
        cudaEventCreateWithFlags(&evFork, cudaEventDisableTiming);
        cudaEventCreateWithFlags(&evJoin, cudaEventDisableTiming);
    }

    // fork: graph preprocessing -> CSR by dst, on side stream
    cudaEventRecord(evFork, 0);
    cudaStreamWaitEvent(s2, evFork, 0);
    k_zero_cnt<<<(NN + 255) / 256, 256, 0, s2>>>();
    k_count<<<(NE + 255) / 256, 256, 0, s2>>>(ei);
    k_dinv<<<(NN + 255) / 256, 256, 0, s2>>>();
    k_scan1<<<NBLK_SCAN, 1024, 0, s2>>>();
    k_scan2<<<1, 32, 0, s2>>>();
    k_scan3<<<(NN + 255) / 256, 256, 0, s2>>>();
    k_fill<<<(NE + 255) / 256, 256, 0, s2>>>(ei);
    cudaEventRecord(evJoin, s2);

    // GEMM1 on main stream (independent of CSR build; CSR build hides under it)
    dim3 g1((NN + 127) / 128, HID / 128);
    k_gemm1_tf32<<<g1, 256>>>(x, W1, b1, NN, HID, INC);

    // join before GEMM2: its fused prescale epilogue needs g_dinv
    cudaStreamWaitEvent(0, evJoin, 0);
    dim3 g2((NN + 127) / 128, 1);
    k_gemm2_tf32<<<g2, 256>>>(W2, b2, NN, OUTC, HID);

    // 10 propagation iterations (ping-pong fp16; last writes fp32 d_out)
    int pgrid = (NN * 32 + 255) / 256;
    k_prop<<<pgrid, 256>>>(0, 1, out);
    k_prop<<<pgrid, 256>>>(1, 2, out);
    k_prop<<<pgrid, 256>>>(2, 1, out);
    k_prop<<<pgrid, 256>>>(1, 2, out);
    k_prop<<<pgrid, 256>>>(2, 1, out);
    k_prop<<<pgrid, 256>>>(1, 2, out);
    k_prop<<<pgrid, 256>>>(2, 1, out);
    k_prop<<<pgrid, 256>>>(1, 2, out);
    k_prop<<<pgrid, 256>>>(2, 1, out);
    k_prop<<<pgrid, 256>>>(1, 3, out);
    (void)in_sizes; (void)n_in; (void)out_size;
}

// round 15
// speedup vs baseline: 1.0356x; 1.0356x over previous
#include <cuda_runtime.h>
#include <cuda_fp16.h>
#include <cstdint>

// Problem constants (fixed by the dataset)
#define NN        100000
#define NE        3200000
#define INC       512
#define HID       256
#define OUTC      64
#define NBLK_SCAN 98      // ceil(NN / 1024)

// ---------------- scratch (static __device__ — no allocations) ----------------
__device__ float   g_hidden[(size_t)NN * HID];     // 102.4 MB
__device__ float   g_h0[(size_t)NN * OUTC];        // 25.6 MB (fp32 residual, final iter)
__device__ __half2 g_h0r16[(size_t)NN * (OUTC/2)]; // fp16 residual (iters 1-9)
__device__ __half2 g_h016[(size_t)NN * (OUTC/2)];  // prescaled fp16 (dinv*h)
__device__ __half2 g_hA16[(size_t)NN * (OUTC/2)];
__device__ __half2 g_hB16[(size_t)NN * (OUTC/2)];
__device__ int     g_cnt[NN];
__device__ int     g_rowptr[NN + 1];
__device__ int     g_fillpos[NN];
__device__ float   g_dinv[NN];
__device__ int     g_esrc[NE];                     // src only, 12.8 MB
__device__ int     g_bsums[NBLK_SCAN];

// ---------------- graph preprocessing ----------------
__global__ void k_zero_cnt() {
    int i = blockIdx.x * blockDim.x + threadIdx.x;
    if (i < NN) g_cnt[i] = 0;
}

// ei is int32 (JAX default x64-disabled downgrades int64 -> int32)
__global__ void k_count(const int* __restrict__ ei) {
    int e = blockIdx.x * blockDim.x + threadIdx.x;
    if (e < NE) {
        int d = ei[NE + e];
        if (d >= 0 && d < NN) atomicAdd(&g_cnt[d], 1);
    }
}

__global__ void k_dinv() {
    int i = blockIdx.x * blockDim.x + threadIdx.x;
    if (i < NN) g_dinv[i] = rsqrtf((float)(g_cnt[i] + 1)); // +1 self loop
}

__global__ void k_scan1() {
    __shared__ int s[1024];
    int tid = threadIdx.x;
    int i = blockIdx.x * 1024 + tid;
    int v = (i < NN) ? g_cnt[i] : 0;
    s[tid] = v;
    __syncthreads();
    for (int off = 1; off < 1024; off <<= 1) {
        int t = (tid >= off) ? s[tid - off] : 0;
        __syncthreads();
        s[tid] += t;
        __syncthreads();
    }
    if (i < NN) g_rowptr[i] = s[tid];
    if (tid == 1023) g_bsums[blockIdx.x] = s[1023];
}

__global__ void k_scan2() {
    if (threadIdx.x == 0) {
        int run = 0;
        for (int b = 0; b < NBLK_SCAN; b++) { int t = g_bsums[b]; g_bsums[b] = run; run += t; }
    }
}

__global__ void k_scan3() {
    int i = blockIdx.x * blockDim.x + threadIdx.x;
    if (i < NN) {
        int ex = g_rowptr[i] - g_cnt[i] + g_bsums[i >> 10]; // global exclusive
        g_rowptr[i]  = ex;
        g_fillpos[i] = ex;
    }
    if (i == 0) g_rowptr[NN] = NE;
}

__global__ void k_fill(const int* __restrict__ ei) {
    int e = blockIdx.x * blockDim.x + threadIdx.x;
    if (e < NE) {
        int s = ei[e];
        int d = ei[NE + e];
        if (s >= 0 && s < NN && d >= 0 && d < NN) {
            int p = atomicAdd(&g_fillpos[d], 1);
            g_esrc[p] = s;
        }
    }
}

// ---------------- tf32 helpers ----------------
__device__ __forceinline__ uint32_t f2tf(float f) {
    uint32_t u;
    asm("cvt.rna.tf32.f32 %0, %1;" : "=r"(u) : "f"(f));
    return u;
}

// ---------------- tf32 tensor-core GEMM1: C = relu(A @ B + bias) --------------
// 128x128 tile, BK=16, 8 warps (4m x 2n), warp tile 32x64, mma.m16n8k8 tf32
__global__ void __launch_bounds__(256) k_gemm1_tf32(
    const float* __restrict__ A, const float* __restrict__ B,
    const float* __restrict__ bias, int M, int N, int K)
{
    float* C = (float*)g_hidden;
    __shared__ uint32_t As[2][128][20];
    __shared__ uint32_t Bs[2][16][136];

    int tid = threadIdx.x;
    int lane = tid & 31, wid = tid >> 5;
    int wm = wid & 3, wn = wid >> 2;
    int g = lane >> 2, t = lane & 3;
    int row0 = blockIdx.x * 128, col0 = blockIdx.y * 128;

    int ar0 = tid >> 2;
    int ac  = (tid & 3) << 2;
    int br0 = tid >> 5;
    int bc  = (tid & 31) << 2;

    const float* Ap0 = A + (size_t)(row0 + ar0) * K + ac;
    const float* Ap1 = A + (size_t)(row0 + ar0 + 64) * K + ac;
    bool aok0 = (row0 + ar0) < M;
    bool aok1 = (row0 + ar0 + 64) < M;
    const float* Bp0 = B + (size_t)br0 * N + col0 + bc;
    const float* Bp1 = B + (size_t)(br0 + 8) * N + col0 + bc;

    float c[2][8][4] = {};

    const float4 fz = make_float4(0.f, 0.f, 0.f, 0.f);
    float4 av0 = aok0 ? *(const float4*)Ap0 : fz;
    float4 av1 = aok1 ? *(const float4*)Ap1 : fz;
    float4 bv0 = *(const float4*)Bp0;
    float4 bv1 = *(const float4*)Bp1;

    int nk = K >> 4;
    for (int kt = 0; kt < nk; kt++) {
        int cur = kt & 1;
        *(uint4*)&As[cur][ar0][ac]      = make_uint4(f2tf(av0.x), f2tf(av0.y), f2tf(av0.z), f2tf(av0.w));
        *(uint4*)&As[cur][ar0 + 64][ac] = make_uint4(f2tf(av1.x), f2tf(av1.y), f2tf(av1.z), f2tf(av1.w));
        *(uint4*)&Bs[cur][br0][bc]      = make_uint4(f2tf(bv0.x), f2tf(bv0.y), f2tf(bv0.z), f2tf(bv0.w));
        *(uint4*)&Bs[cur][br0 + 8][bc]  = make_uint4(f2tf(bv1.x), f2tf(bv1.y), f2tf(bv1.z), f2tf(bv1.w));
        __syncthreads();

        if (kt + 1 < nk) {
            int ko = (kt + 1) << 4;
            av0 = aok0 ? *(const float4*)(Ap0 + ko) : fz;
            av1 = aok1 ? *(const float4*)(Ap1 + ko) : fz;
            bv0 = *(const float4*)(Bp0 + (size_t)ko * N);
            bv1 = *(const float4*)(Bp1 + (size_t)ko * N);
        }

#pragma unroll
        for (int ks = 0; ks < 2; ks++) {
            int k = ks << 3;
            uint32_t af[2][4];
#pragma unroll
            for (int mi = 0; mi < 2; mi++) {
                int m0 = wm * 32 + mi * 16;
                af[mi][0] = As[cur][m0 + g][k + t];
                af[mi][1] = As[cur][m0 + g + 8][k + t];
                af[mi][2] = As[cur][m0 + g][k + t + 4];
                af[mi][3] = As[cur][m0 + g + 8][k + t + 4];
            }
            uint32_t bf[8][2];
#pragma unroll
            for (int ni = 0; ni < 8; ni++) {
                int n0 = wn * 64 + ni * 8;
                bf[ni][0] = Bs[cur][k + t][n0 + g];
                bf[ni][1] = Bs[cur][k + t + 4][n0 + g];
            }
#pragma unroll
            for (int mi = 0; mi < 2; mi++)
#pragma unroll
                for (int ni = 0; ni < 8; ni++) {
                    asm volatile(
                        "mma.sync.aligned.m16n8k8.row.col.f32.tf32.tf32.f32 "
                        "{%0,%1,%2,%3}, {%4,%5,%6,%7}, {%8,%9}, {%0,%1,%2,%3};"
                        : "+f"(c[mi][ni][0]), "+f"(c[mi][ni][1]),
                          "+f"(c[mi][ni][2]), "+f"(c[mi][ni][3])
                        : "r"(af[mi][0]), "r"(af[mi][1]), "r"(af[mi][2]), "r"(af[mi][3]),
                          "r"(bf[ni][0]), "r"(bf[ni][1]));
                }
        }
        __syncthreads();
    }

#pragma unroll
    for (int mi = 0; mi < 2; mi++) {
        int r = row0 + wm * 32 + mi * 16 + g;
#pragma unroll
        for (int ni = 0; ni < 8; ni++) {
            int cn = col0 + wn * 64 + ni * 8 + (t << 1);
            float2 bb = *(const float2*)&bias[cn];
            if (r < M) {
                float2 o;
                o.x = fmaxf(c[mi][ni][0] + bb.x, 0.f);
                o.y = fmaxf(c[mi][ni][1] + bb.y, 0.f);
                *(float2*)&C[(size_t)r * N + cn] = o;
            }
            if (r + 8 < M) {
                float2 o;
                o.x = fmaxf(c[mi][ni][2] + bb.x, 0.f);
                o.y = fmaxf(c[mi][ni][3] + bb.y, 0.f);
                *(float2*)&C[(size_t)(r + 8) * N + cn] = o;
            }
        }
    }
}

// ---------------- tf32 tensor-core GEMM2 (+fused prescale epilogue) ------------
// g_h0 = g_hidden @ W2 + b2 ; also emits g_h0r16 (fp16 h0) and g_h016 (fp16 dinv*h0)
// 128x64 tile, BK=16, 8 warps (4m x 2n), warp tile 32x32
__global__ void __launch_bounds__(256) k_gemm2_tf32(
    const float* __restrict__ B, const float* __restrict__ bias,
    int M, int N, int K)
{
    const float* A = (const float*)g_hidden;
    float* C = (float*)g_h0;
    __shared__ uint32_t As[2][128][20];
    __shared__ uint32_t Bs[2][16][72];

    int tid = threadIdx.x;
    int lane = tid & 31, wid = tid >> 5;
    int wm = wid & 3, wn = wid >> 2;
    int g = lane >> 2, t = lane & 3;
    int row0 = blockIdx.x * 128;

    int ar0 = tid >> 2;
    int ac  = (tid & 3) << 2;
    int br0 = tid >> 4;
    int bc  = (tid & 15) << 2;

    const float* Ap0 = A + (size_t)(row0 + ar0) * K + ac;
    const float* Ap1 = A + (size_t)(row0 + ar0 + 64) * K + ac;
    bool aok0 = (row0 + ar0) < M;
    bool aok1 = (row0 + ar0 + 64) < M;
    const float* Bp = B + (size_t)br0 * N + bc;

    float c[2][4][4] = {};

    const float4 fz = make_float4(0.f, 0.f, 0.f, 0.f);
    float4 av0 = aok0 ? *(const float4*)Ap0 : fz;
    float4 av1 = aok1 ? *(const float4*)Ap1 : fz;
    float4 bv = *(const float4*)Bp;

    int nk = K >> 4;
    for (int kt = 0; kt < nk; kt++) {
        int cur = kt & 1;
        *(uint4*)&As[cur][ar0][ac]      = make_uint4(f2tf(av0.x), f2tf(av0.y), f2tf(av0.z), f2tf(av0.w));
        *(uint4*)&As[cur][ar0 + 64][ac] = make_uint4(f2tf(av1.x), f2tf(av1.y), f2tf(av1.z), f2tf(av1.w));
        *(uint4*)&Bs[cur][br0][bc]      = make_uint4(f2tf(bv.x), f2tf(bv.y), f2tf(bv.z), f2tf(bv.w));
        __syncthreads();

        if (kt + 1 < nk) {
            int ko = (kt + 1) << 4;
            av0 = aok0 ? *(const float4*)(Ap0 + ko) : fz;
            av1 = aok1 ? *(const float4*)(Ap1 + ko) : fz;
            bv = *(const float4*)(Bp + (size_t)ko * N);
        }

#pragma unroll
        for (int ks = 0; ks < 2; ks++) {
            int k = ks << 3;
            uint32_t af[2][4];
#pragma unroll
            for (int mi = 0; mi < 2; mi++) {
                int m0 = wm * 32 + mi * 16;
                af[mi][0] = As[cur][m0 + g][k + t];
                af[mi][1] = As[cur][m0 + g + 8][k + t];
                af[mi][2] = As[cur][m0 + g][k + t + 4];
                af[mi][3] = As[cur][m0 + g + 8][k + t + 4];
            }
            uint32_t bf[4][2];
#pragma unroll
            for (int ni = 0; ni < 4; ni++) {
                int n0 = wn * 32 + ni * 8;
                bf[ni][0] = Bs[cur][k + t][n0 + g];
                bf[ni][1] = Bs[cur][k + t + 4][n0 + g];
            }
#pragma unroll
            for (int mi = 0; mi < 2; mi++)
#pragma unroll
                for (int ni = 0; ni < 4; ni++) {
                    asm volatile(
                        "mma.sync.aligned.m16n8k8.row.col.f32.tf32.tf32.f32 "
                        "{%0,%1,%2,%3}, {%4,%5,%6,%7}, {%8,%9}, {%0,%1,%2,%3};"
                        : "+f"(c[mi][ni][0]), "+f"(c[mi][ni][1]),
                          "+f"(c[mi][ni][2]), "+f"(c[mi][ni][3])
                        : "r"(af[mi][0]), "r"(af[mi][1]), "r"(af[mi][2]), "r"(af[mi][3]),
                          "r"(bf[ni][0]), "r"(bf[ni][1]));
                }
        }
        __syncthreads();
    }

#pragma unroll
    for (int mi = 0; mi < 2; mi++) {
        int r0 = row0 + wm * 32 + mi * 16 + g;
        float dv0 = (r0 < M) ? g_dinv[r0] : 0.f;
        float dv1 = (r0 + 8 < M) ? g_dinv[r0 + 8] : 0.f;
#pragma unroll
        for (int ni = 0; ni < 4; ni++) {
            int cn = wn * 32 + ni * 8 + (t << 1);
            float2 bb = *(const float2*)&bias[cn];
            if (r0 < M) {
                float2 o;
                o.x = c[mi][ni][0] + bb.x;
                o.y = c[mi][ni][1] + bb.y;
                *(float2*)&C[(size_t)r0 * N + cn] = o;
                size_t hi = (size_t)r0 * (OUTC / 2) + (cn >> 1);
                g_h0r16[hi] = __floats2half2_rn(o.x, o.y);
                g_h016[hi]  = __floats2half2_rn(dv0 * o.x, dv0 * o.y);
            }
            if (r0 + 8 < M) {
                float2 o;
                o.x = c[mi][ni][2] + bb.x;
                o.y = c[mi][ni][3] + bb.y;
                *(float2*)&C[(size_t)(r0 + 8) * N + cn] = o;
                size_t hi = (size_t)(r0 + 8) * (OUTC / 2) + (cn >> 1);
                g_h0r16[hi] = __floats2half2_rn(o.x, o.y);
                g_h016[hi]  = __floats2half2_rn(dv1 * o.x, dv1 * o.y);
            }
        }
    }
}

// ---------------- propagation ----------------
// gather buffers hold hs = dinv * h (prescaled). Per node d:
//   agg = dinv_d * ( sum_{in-edges} hs[s] + hs[d] )
//   h_next = 0.9*agg + 0.1*h0;  store dinv_d*h_next (fp16) or h_next (fp32 final)
// warp/node; 16-lane half-warps each process one edge per step; lane (sub,c)
// accumulates cols 4c..4c+3 in fp32; cross-half merge via shfl_xor(16).
// (round-12 loop body — the fp16-accum variant regressed; prop is L2-bound)
__global__ void __launch_bounds__(256) k_prop(int src_id, int dst_id,
                                              float* __restrict__ ext_out)
{
    const __half2* hin = (src_id == 0) ? (const __half2*)g_h016
                       : (src_id == 1) ? (const __half2*)g_hA16
                                       : (const __half2*)g_hB16;
    __half2* hout16 = (dst_id == 1) ? (__half2*)g_hA16
                    : (dst_id == 2) ? (__half2*)g_hB16
                                    : nullptr;

    int node = (blockIdx.x * blockDim.x + threadIdx.x) >> 5;
    int lane = threadIdx.x & 31;
    if (node >= NN) return;
    int sub = lane >> 4;           // which edge of the pair
    int c   = lane & 15;           // column group: cols 4c..4c+3
    int beg = g_rowptr[node];
    int end = g_rowptr[node + 1];

    float a0 = 0.f, a1 = 0.f, a2 = 0.f, a3 = 0.f;
    for (int base = beg; base < end; base += 32) {
        int nb = end - base; if (nb > 32) nb = 32;
        int es = 0;
        if (lane < nb) es = g_esrc[base + lane];
#pragma unroll 4
        for (int j = 0; j < 16; j++) {
            int e = (j << 1) + sub;
            int s = __shfl_sync(0xffffffffu, es, e);
            if (e < nb) {
                const __half2* hp = hin + (size_t)s * (OUTC / 2) + (c << 1);
                uint2 raw = *(const uint2*)hp;
                float2 f0 = __half22float2(*(__half2*)&raw.x);
                float2 f1 = __half22float2(*(__half2*)&raw.y);
                a0 += f0.x; a1 += f0.y; a2 += f1.x; a3 += f1.y;
            }
            if ((j << 1) + 2 >= nb) break;
        }
    }
    // merge the two half-warp partial sums
    a0 += __shfl_xor_sync(0xffffffffu, a0, 16);
    a1 += __shfl_xor_sync(0xffffffffu, a1, 16);
    a2 += __shfl_xor_sync(0xffffffffu, a2, 16);
    a3 += __shfl_xor_sync(0xffffffffu, a3, 16);

    if (sub == 0) {
        float dv = g_dinv[node];
        // self loop (prescaled row)
        uint2 sraw = *(const uint2*)(hin + (size_t)node * (OUTC / 2) + (c << 1));
        float2 s0 = __half22float2(*(__half2*)&sraw.x);
        float2 s1 = __half22float2(*(__half2*)&sraw.y);
        a0 += s0.x; a1 += s0.y; a2 += s1.x; a3 += s1.y;

        if (hout16) {
            // residual from fp16 h0 copy
            uint2 rraw = *(const uint2*)(g_h0r16 + (size_t)node * (OUTC / 2) + (c << 1));
            float2 r0 = __half22float2(*(__half2*)&rraw.x);
            float2 r1 = __half22float2(*(__half2*)&rraw.y);
            float o0 = 0.9f * dv * a0 + 0.1f * r0.x;
            float o1 = 0.9f * dv * a1 + 0.1f * r0.y;
            float o2 = 0.9f * dv * a2 + 0.1f * r1.x;
            float o3 = 0.9f * dv * a3 + 0.1f * r1.y;
            __half2* op = hout16 + (size_t)node * (OUTC / 2) + (c << 1);
            uint2 ow;
            *(__half2*)&ow.x = __floats2half2_rn(dv * o0, dv * o1);
            *(__half2*)&ow.y = __floats2half2_rn(dv * o2, dv * o3);
            *(uint2*)op = ow;
        } else {
            // final iteration: fp32 residual, fp32 output
            float4 h0v = *(const float4*)(g_h0 + (size_t)node * OUTC + (c << 2));
            float o0 = 0.9f * dv * a0 + 0.1f * h0v.x;
            float o1 = 0.9f * dv * a1 + 0.1f * h0v.y;
            float o2 = 0.9f * dv * a2 + 0.1f * h0v.z;
            float o3 = 0.9f * dv * a3 + 0.1f * h0v.w;
            *(float4*)(ext_out + (size_t)node * OUTC + (c << 2)) =
                make_float4(o0, o1, o2, o3);
        }
    }
}

// ---------------- launch ----------------
extern "C" void kernel_launch(void* const* d_in, const int* in_sizes, int n_in,
                              void* d_out, int out_size)
{
    const float* x  = (const float*)d_in[0];
    const int*   ei = (const int*)d_in[1];     // int32 (JAX x64 disabled)
    const float* W1 = (const float*)d_in[2];
    const float* b1 = (const float*)d_in[3];
    const float* W2 = (const float*)d_in[4];
    const float* b2 = (const float*)d_in[5];
    float* out = (float*)d_out;

    static cudaStream_t s2 = nullptr;
    static cudaEvent_t evFork = nullptr, evJoin = nullptr;
    if (s2 == nullptr) {
        cudaStreamCreateWithFlags(&s2, cudaStreamNonBlocking);
        cudaEventCreateWithFlags(&evFork, cudaEventDisableTiming);
        cudaEventCreateWithFlags(&evJoin, cudaEventDisableTiming);
    }

    // fork: graph preprocessing -> CSR by dst, on side stream
    cudaEventRecord(evFork, 0);
    cudaStreamWaitEvent(s2, evFork, 0);
    k_zero_cnt<<<(NN + 255) / 256, 256, 0, s2>>>();
    k_count<<<(NE + 255) / 256, 256, 0, s2>>>(ei);
    k_dinv<<<(NN + 255) / 256, 256, 0, s2>>>();
    k_scan1<<<NBLK_SCAN, 1024, 0, s2>>>();
    k_scan2<<<1, 32, 0, s2>>>();
    k_scan3<<<(NN + 255) / 256, 256, 0, s2>>>();
    k_fill<<<(NE + 255) / 256, 256, 0, s2>>>(ei);
    cudaEventRecord(evJoin, s2);

    // GEMM1 on main stream (independent of CSR build; CSR build hides under it)
    dim3 g1((NN + 127) / 128, HID / 128);
    k_gemm1_tf32<<<g1, 256>>>(x, W1, b1, NN, HID, INC);

    // join before GEMM2: its fused prescale epilogue needs g_dinv
    cudaStreamWaitEvent(0, evJoin, 0);
    dim3 g2((NN + 127) / 128, 1);
    k_gemm2_tf32<<<g2, 256>>>(W2, b2, NN, OUTC, HID);

    // 10 propagation iterations (ping-pong fp16; last writes fp32 d_out)
    int pgrid = (NN * 32 + 255) / 256;
    k_prop<<<pgrid, 256>>>(0, 1, out);
    k_prop<<<pgrid, 256>>>(1, 2, out);
    k_prop<<<pgrid, 256>>>(2, 1, out);
    k_prop<<<pgrid, 256>>>(1, 2, out);
    k_prop<<<pgrid, 256>>>(2, 1, out);
    k_prop<<<pgrid, 256>>>(1, 2, out);
    k_prop<<<pgrid, 256>>>(2, 1, out);
    k_prop<<<pgrid, 256>>>(1, 2, out);
    k_prop<<<pgrid, 256>>>(2, 1, out);
    k_prop<<<pgrid, 256>>>(1, 3, out);
    (void)in_sizes; (void)n_in; (void)out_size;
}

// round 16
// speedup vs baseline: 1.1871x; 1.1463x over previous
#include <cuda_runtime.h>
#include <cuda_fp16.h>
#include <cstdint>

// Problem constants (fixed by the dataset)
#define NN        100000
#define NE        3200000
#define INC       512
#define HID       256
#define OUTC      64
#define NBLK_SCAN 98      // ceil(NN / 1024)

// ---------------- scratch (static __device__ — no allocations) ----------------
__device__ float   g_hidden[(size_t)NN * HID];     // 102.4 MB
__device__ float   g_h0[(size_t)NN * OUTC];        // 25.6 MB (fp32 residual, final iter)
__device__ __half2 g_h0r16[(size_t)NN * (OUTC/2)]; // fp16 residual (iters 1-9)
__device__ __half2 g_h016[(size_t)NN * (OUTC/2)];  // prescaled fp16 (dinv*h)
__device__ __half2 g_hA16[(size_t)NN * (OUTC/2)];
__device__ __half2 g_hB16[(size_t)NN * (OUTC/2)];
__device__ int     g_cnt[NN];
__device__ int     g_rowptr[NN + 1];
__device__ int     g_fillpos[NN];
__device__ float   g_dinv[NN];
__device__ int     g_esrc[NE];                     // src only, 12.8 MB
__device__ int     g_bsums[NBLK_SCAN];

// ---------------- graph preprocessing ----------------
__global__ void k_zero_cnt() {
    int i = blockIdx.x * blockDim.x + threadIdx.x;
    if (i < NN) g_cnt[i] = 0;
}

// ei is int32 (JAX default x64-disabled downgrades int64 -> int32)
__global__ void k_count(const int* __restrict__ ei) {
    int e = blockIdx.x * blockDim.x + threadIdx.x;
    if (e < NE) {
        int d = ei[NE + e];
        if (d >= 0 && d < NN) atomicAdd(&g_cnt[d], 1);
    }
}

__global__ void k_dinv() {
    int i = blockIdx.x * blockDim.x + threadIdx.x;
    if (i < NN) g_dinv[i] = rsqrtf((float)(g_cnt[i] + 1)); // +1 self loop
}

__global__ void k_scan1() {
    __shared__ int s[1024];
    int tid = threadIdx.x;
    int i = blockIdx.x * 1024 + tid;
    int v = (i < NN) ? g_cnt[i] : 0;
    s[tid] = v;
    __syncthreads();
    for (int off = 1; off < 1024; off <<= 1) {
        int t = (tid >= off) ? s[tid - off] : 0;
        __syncthreads();
        s[tid] += t;
        __syncthreads();
    }
    if (i < NN) g_rowptr[i] = s[tid];
    if (tid == 1023) g_bsums[blockIdx.x] = s[1023];
}

__global__ void k_scan2() {
    if (threadIdx.x == 0) {
        int run = 0;
        for (int b = 0; b < NBLK_SCAN; b++) { int t = g_bsums[b]; g_bsums[b] = run; run += t; }
    }
}

__global__ void k_scan3() {
    int i = blockIdx.x * blockDim.x + threadIdx.x;
    if (i < NN) {
        int ex = g_rowptr[i] - g_cnt[i] + g_bsums[i >> 10]; // global exclusive
        g_rowptr[i]  = ex;
        g_fillpos[i] = ex;
    }
    if (i == 0) g_rowptr[NN] = NE;
}

__global__ void k_fill(const int* __restrict__ ei) {
    int e = blockIdx.x * blockDim.x + threadIdx.x;
    if (e < NE) {
        int s = ei[e];
        int d = ei[NE + e];
        if (s >= 0 && s < NN && d >= 0 && d < NN) {
            int p = atomicAdd(&g_fillpos[d], 1);
            g_esrc[p] = s;
        }
    }
}

// prescale h0 -> fp16 buffers: g_h016 = dinv*h0, g_h0r16 = h0 (both coalesced)
__global__ void k_prescale() {
    int idx = blockIdx.x * blockDim.x + threadIdx.x;   // over NN*32 half2
    if (idx < NN * (OUTC / 2)) {
        int node = idx >> 5;
        float dv = g_dinv[node];
        float2 f = *(const float2*)(g_h0 + ((size_t)idx << 1));
        g_h016[idx]  = __floats2half2_rn(dv * f.x, dv * f.y);
        g_h0r16[idx] = __floats2half2_rn(f.x, f.y);
    }
}

// ---------------- tf32 helpers ----------------
__device__ __forceinline__ uint32_t f2tf(float f) {
    uint32_t u;
    asm("cvt.rna.tf32.f32 %0, %1;" : "=r"(u) : "f"(f));
    return u;
}

// ---------------- tf32 tensor-core GEMM1: C = relu(A @ B + bias) --------------
// 128x128 tile, BK=16, 8 warps (4m x 2n), warp tile 32x64, mma.m16n8k8 tf32
__global__ void __launch_bounds__(256) k_gemm1_tf32(
    const float* __restrict__ A, const float* __restrict__ B,
    const float* __restrict__ bias, int M, int N, int K)
{
    float* C = (float*)g_hidden;
    __shared__ uint32_t As[2][128][20];
    __shared__ uint32_t Bs[2][16][136];

    int tid = threadIdx.x;
    int lane = tid & 31, wid = tid >> 5;
    int wm = wid & 3, wn = wid >> 2;
    int g = lane >> 2, t = lane & 3;
    int row0 = blockIdx.x * 128, col0 = blockIdx.y * 128;

    int ar0 = tid >> 2;
    int ac  = (tid & 3) << 2;
    int br0 = tid >> 5;
    int bc  = (tid & 31) << 2;

    const float* Ap0 = A + (size_t)(row0 + ar0) * K + ac;
    const float* Ap1 = A + (size_t)(row0 + ar0 + 64) * K + ac;
    bool aok0 = (row0 + ar0) < M;
    bool aok1 = (row0 + ar0 + 64) < M;
    const float* Bp0 = B + (size_t)br0 * N + col0 + bc;
    const float* Bp1 = B + (size_t)(br0 + 8) * N + col0 + bc;

    float c[2][8][4] = {};

    const float4 fz = make_float4(0.f, 0.f, 0.f, 0.f);
    float4 av0 = aok0 ? *(const float4*)Ap0 : fz;
    float4 av1 = aok1 ? *(const float4*)Ap1 : fz;
    float4 bv0 = *(const float4*)Bp0;
    float4 bv1 = *(const float4*)Bp1;

    int nk = K >> 4;
    for (int kt = 0; kt < nk; kt++) {
        int cur = kt & 1;
        *(uint4*)&As[cur][ar0][ac]      = make_uint4(f2tf(av0.x), f2tf(av0.y), f2tf(av0.z), f2tf(av0.w));
        *(uint4*)&As[cur][ar0 + 64][ac] = make_uint4(f2tf(av1.x), f2tf(av1.y), f2tf(av1.z), f2tf(av1.w));
        *(uint4*)&Bs[cur][br0][bc]      = make_uint4(f2tf(bv0.x), f2tf(bv0.y), f2tf(bv0.z), f2tf(bv0.w));
        *(uint4*)&Bs[cur][br0 + 8][bc]  = make_uint4(f2tf(bv1.x), f2tf(bv1.y), f2tf(bv1.z), f2tf(bv1.w));
        __syncthreads();

        if (kt + 1 < nk) {
            int ko = (kt + 1) << 4;
            av0 = aok0 ? *(const float4*)(Ap0 + ko) : fz;
            av1 = aok1 ? *(const float4*)(Ap1 + ko) : fz;
            bv0 = *(const float4*)(Bp0 + (size_t)ko * N);
            bv1 = *(const float4*)(Bp1 + (size_t)ko * N);
        }

#pragma unroll
        for (int ks = 0; ks < 2; ks++) {
            int k = ks << 3;
            uint32_t af[2][4];
#pragma unroll
            for (int mi = 0; mi < 2; mi++) {
                int m0 = wm * 32 + mi * 16;
                af[mi][0] = As[cur][m0 + g][k + t];
                af[mi][1] = As[cur][m0 + g + 8][k + t];
                af[mi][2] = As[cur][m0 + g][k + t + 4];
                af[mi][3] = As[cur][m0 + g + 8][k + t + 4];
            }
            uint32_t bf[8][2];
#pragma unroll
            for (int ni = 0; ni < 8; ni++) {
                int n0 = wn * 64 + ni * 8;
                bf[ni][0] = Bs[cur][k + t][n0 + g];
                bf[ni][1] = Bs[cur][k + t + 4][n0 + g];
            }
#pragma unroll
            for (int mi = 0; mi < 2; mi++)
#pragma unroll
                for (int ni = 0; ni < 8; ni++) {
                    asm volatile(
                        "mma.sync.aligned.m16n8k8.row.col.f32.tf32.tf32.f32 "
                        "{%0,%1,%2,%3}, {%4,%5,%6,%7}, {%8,%9}, {%0,%1,%2,%3};"
                        : "+f"(c[mi][ni][0]), "+f"(c[mi][ni][1]),
                          "+f"(c[mi][ni][2]), "+f"(c[mi][ni][3])
                        : "r"(af[mi][0]), "r"(af[mi][1]), "r"(af[mi][2]), "r"(af[mi][3]),
                          "r"(bf[ni][0]), "r"(bf[ni][1]));
                }
        }
        __syncthreads();
    }

#pragma unroll
    for (int mi = 0; mi < 2; mi++) {
        int r = row0 + wm * 32 + mi * 16 + g;
#pragma unroll
        for (int ni = 0; ni < 8; ni++) {
            int cn = col0 + wn * 64 + ni * 8 + (t << 1);
            float2 bb = *(const float2*)&bias[cn];
            if (r < M) {
                float2 o;
                o.x = fmaxf(c[mi][ni][0] + bb.x, 0.f);
                o.y = fmaxf(c[mi][ni][1] + bb.y, 0.f);
                *(float2*)&C[(size_t)r * N + cn] = o;
            }
            if (r + 8 < M) {
                float2 o;
                o.x = fmaxf(c[mi][ni][2] + bb.x, 0.f);
                o.y = fmaxf(c[mi][ni][3] + bb.y, 0.f);
                *(float2*)&C[(size_t)(r + 8) * N + cn] = o;
            }
        }
    }
}

// ---------------- tf32 tensor-core GEMM2: g_h0 = g_hidden @ W2 + b2 ------------
// 128x64 tile, BK=16, 8 warps (4m x 2n), warp tile 32x32
__global__ void __launch_bounds__(256) k_gemm2_tf32(
    const float* __restrict__ B, const float* __restrict__ bias,
    int M, int N, int K)
{
    const float* A = (const float*)g_hidden;
    float* C = (float*)g_h0;
    __shared__ uint32_t As[2][128][20];
    __shared__ uint32_t Bs[2][16][72];

    int tid = threadIdx.x;
    int lane = tid & 31, wid = tid >> 5;
    int wm = wid & 3, wn = wid >> 2;
    int g = lane >> 2, t = lane & 3;
    int row0 = blockIdx.x * 128;

    int ar0 = tid >> 2;
    int ac  = (tid & 3) << 2;
    int br0 = tid >> 4;
    int bc  = (tid & 15) << 2;

    const float* Ap0 = A + (size_t)(row0 + ar0) * K + ac;
    const float* Ap1 = A + (size_t)(row0 + ar0 + 64) * K + ac;
    bool aok0 = (row0 + ar0) < M;
    bool aok1 = (row0 + ar0 + 64) < M;
    const float* Bp = B + (size_t)br0 * N + bc;

    float c[2][4][4] = {};

    const float4 fz = make_float4(0.f, 0.f, 0.f, 0.f);
    float4 av0 = aok0 ? *(const float4*)Ap0 : fz;
    float4 av1 = aok1 ? *(const float4*)Ap1 : fz;
    float4 bv = *(const float4*)Bp;

    int nk = K >> 4;
    for (int kt = 0; kt < nk; kt++) {
        int cur = kt & 1;
        *(uint4*)&As[cur][ar0][ac]      = make_uint4(f2tf(av0.x), f2tf(av0.y), f2tf(av0.z), f2tf(av0.w));
        *(uint4*)&As[cur][ar0 + 64][ac] = make_uint4(f2tf(av1.x), f2tf(av1.y), f2tf(av1.z), f2tf(av1.w));
        *(uint4*)&Bs[cur][br0][bc]      = make_uint4(f2tf(bv.x), f2tf(bv.y), f2tf(bv.z), f2tf(bv.w));
        __syncthreads();

        if (kt + 1 < nk) {
            int ko = (kt + 1) << 4;
            av0 = aok0 ? *(const float4*)(Ap0 + ko) : fz;
            av1 = aok1 ? *(const float4*)(Ap1 + ko) : fz;
            bv = *(const float4*)(Bp + (size_t)ko * N);
        }

#pragma unroll
        for (int ks = 0; ks < 2; ks++) {
            int k = ks << 3;
            uint32_t af[2][4];
#pragma unroll
            for (int mi = 0; mi < 2; mi++) {
                int m0 = wm * 32 + mi * 16;
                af[mi][0] = As[cur][m0 + g][k + t];
                af[mi][1] = As[cur][m0 + g + 8][k + t];
                af[mi][2] = As[cur][m0 + g][k + t + 4];
                af[mi][3] = As[cur][m0 + g + 8][k + t + 4];
            }
            uint32_t bf[4][2];
#pragma unroll
            for (int ni = 0; ni < 4; ni++) {
                int n0 = wn * 32 + ni * 8;
                bf[ni][0] = Bs[cur][k + t][n0 + g];
                bf[ni][1] = Bs[cur][k + t + 4][n0 + g];
            }
#pragma unroll
            for (int mi = 0; mi < 2; mi++)
#pragma unroll
                for (int ni = 0; ni < 4; ni++) {
                    asm volatile(
                        "mma.sync.aligned.m16n8k8.row.col.f32.tf32.tf32.f32 "
                        "{%0,%1,%2,%3}, {%4,%5,%6,%7}, {%8,%9}, {%0,%1,%2,%3};"
                        : "+f"(c[mi][ni][0]), "+f"(c[mi][ni][1]),
                          "+f"(c[mi][ni][2]), "+f"(c[mi][ni][3])
                        : "r"(af[mi][0]), "r"(af[mi][1]), "r"(af[mi][2]), "r"(af[mi][3]),
                          "r"(bf[ni][0]), "r"(bf[ni][1]));
                }
        }
        __syncthreads();
    }

#pragma unroll
    for (int mi = 0; mi < 2; mi++) {
        int r0 = row0 + wm * 32 + mi * 16 + g;
#pragma unroll
        for (int ni = 0; ni < 4; ni++) {
            int cn = wn * 32 + ni * 8 + (t << 1);
            float2 bb = *(const float2*)&bias[cn];
            if (r0 < M) {
                float2 o;
                o.x = c[mi][ni][0] + bb.x;
                o.y = c[mi][ni][1] + bb.y;
                *(float2*)&C[(size_t)r0 * N + cn] = o;
            }
            if (r0 + 8 < M) {
                float2 o;
                o.x = c[mi][ni][2] + bb.x;
                o.y = c[mi][ni][3] + bb.y;
                *(float2*)&C[(size_t)(r0 + 8) * N + cn] = o;
            }
        }
    }
}

// ---------------- propagation ----------------
// gather buffers hold hs = dinv * h (prescaled). Per node d:
//   agg = dinv_d * ( sum_{in-edges} hs[s] + hs[d] )
//   h_next = 0.9*agg + 0.1*h0;  store dinv_d*h_next (fp16) or h_next (fp32 final)
// warp/node; 8 lanes per edge (LDG.128 = 16B/lane covers the 128B row),
// 4 edges per warp-step; fp32 accumulation; two-level shfl_xor(8,16) merge.
__global__ void __launch_bounds__(256) k_prop(int src_id, int dst_id,
                                              float* __restrict__ ext_out)
{
    const __half2* hin = (src_id == 0) ? (const __half2*)g_h016
                       : (src_id == 1) ? (const __half2*)g_hA16
                                       : (const __half2*)g_hB16;
    __half2* hout16 = (dst_id == 1) ? (__half2*)g_hA16
                    : (dst_id == 2) ? (__half2*)g_hB16
                                    : nullptr;

    int node = (blockIdx.x * blockDim.x + threadIdx.x) >> 5;
    int lane = threadIdx.x & 31;
    if (node >= NN) return;
    int sub = lane >> 3;           // edge slot 0..3
    int c   = lane & 7;            // 16-byte chunk: cols 8c..8c+7
    int beg = g_rowptr[node];
    int end = g_rowptr[node + 1];

    float a0 = 0.f, a1 = 0.f, a2 = 0.f, a3 = 0.f;
    float a4 = 0.f, a5 = 0.f, a6 = 0.f, a7 = 0.f;

    for (int base = beg; base < end; base += 32) {
        int nb = end - base; if (nb > 32) nb = 32;
        int es = 0;
        if (lane < nb) es = g_esrc[base + lane];
#pragma unroll
        for (int j = 0; j < 8; j++) {           // 8 steps x 4 edges
            int e = (j << 2) + sub;
            int s = __shfl_sync(0xffffffffu, es, e);
            if (e < nb) {
                uint4 raw = *(const uint4*)(hin + (size_t)s * (OUTC / 2) + (c << 2));
                float2 f0 = __half22float2(*(__half2*)&raw.x);
                float2 f1 = __half22float2(*(__half2*)&raw.y);
                float2 f2 = __half22float2(*(__half2*)&raw.z);
                float2 f3 = __half22float2(*(__half2*)&raw.w);
                a0 += f0.x; a1 += f0.y; a2 += f1.x; a3 += f1.y;
                a4 += f2.x; a5 += f2.y; a6 += f3.x; a7 += f3.y;
            }
            if ((j << 2) + 4 >= nb) break;
        }
    }
    // merge the four quarter-warp partial sums
    a0 += __shfl_xor_sync(0xffffffffu, a0, 8);
    a1 += __shfl_xor_sync(0xffffffffu, a1, 8);
    a2 += __shfl_xor_sync(0xffffffffu, a2, 8);
    a3 += __shfl_xor_sync(0xffffffffu, a3, 8);
    a4 += __shfl_xor_sync(0xffffffffu, a4, 8);
    a5 += __shfl_xor_sync(0xffffffffu, a5, 8);
    a6 += __shfl_xor_sync(0xffffffffu, a6, 8);
    a7 += __shfl_xor_sync(0xffffffffu, a7, 8);
    a0 += __shfl_xor_sync(0xffffffffu, a0, 16);
    a1 += __shfl_xor_sync(0xffffffffu, a1, 16);
    a2 += __shfl_xor_sync(0xffffffffu, a2, 16);
    a3 += __shfl_xor_sync(0xffffffffu, a3, 16);
    a4 += __shfl_xor_sync(0xffffffffu, a4, 16);
    a5 += __shfl_xor_sync(0xffffffffu, a5, 16);
    a6 += __shfl_xor_sync(0xffffffffu, a6, 16);
    a7 += __shfl_xor_sync(0xffffffffu, a7, 16);

    if (sub == 0) {
        float dv = g_dinv[node];
        // self loop (prescaled row)
        uint4 sraw = *(const uint4*)(hin + (size_t)node * (OUTC / 2) + (c << 2));
        {
            float2 f0 = __half22float2(*(__half2*)&sraw.x);
            float2 f1 = __half22float2(*(__half2*)&sraw.y);
            float2 f2 = __half22float2(*(__half2*)&sraw.z);
            float2 f3 = __half22float2(*(__half2*)&sraw.w);
            a0 += f0.x; a1 += f0.y; a2 += f1.x; a3 += f1.y;
            a4 += f2.x; a5 += f2.y; a6 += f3.x; a7 += f3.y;
        }

        if (hout16) {
            // residual from fp16 h0 copy
            uint4 rraw = *(const uint4*)(g_h0r16 + (size_t)node * (OUTC / 2) + (c << 2));
            float2 r0 = __half22float2(*(__half2*)&rraw.x);
            float2 r1 = __half22float2(*(__half2*)&rraw.y);
            float2 r2 = __half22float2(*(__half2*)&rraw.z);
            float2 r3 = __half22float2(*(__half2*)&rraw.w);
            float o0 = 0.9f * dv * a0 + 0.1f * r0.x;
            float o1 = 0.9f * dv * a1 + 0.1f * r0.y;
            float o2 = 0.9f * dv * a2 + 0.1f * r1.x;
            float o3 = 0.9f * dv * a3 + 0.1f * r1.y;
            float o4 = 0.9f * dv * a4 + 0.1f * r2.x;
            float o5 = 0.9f * dv * a5 + 0.1f * r2.y;
            float o6 = 0.9f * dv * a6 + 0.1f * r3.x;
            float o7 = 0.9f * dv * a7 + 0.1f * r3.y;
            uint4 ow;
            *(__half2*)&ow.x = __floats2half2_rn(dv * o0, dv * o1);
            *(__half2*)&ow.y = __floats2half2_rn(dv * o2, dv * o3);
            *(__half2*)&ow.z = __floats2half2_rn(dv * o4, dv * o5);
            *(__half2*)&ow.w = __floats2half2_rn(dv * o6, dv * o7);
            *(uint4*)(hout16 + (size_t)node * (OUTC / 2) + (c << 2)) = ow;
        } else {
            // final iteration: fp32 residual, fp32 output
            const float* h0p = g_h0 + (size_t)node * OUTC + (c << 3);
            float4 hv0 = *(const float4*)h0p;
            float4 hv1 = *(const float4*)(h0p + 4);
            float* op = ext_out + (size_t)node * OUTC + (c << 3);
            *(float4*)op = make_float4(0.9f * dv * a0 + 0.1f * hv0.x,
                                       0.9f * dv * a1 + 0.1f * hv0.y,
                                       0.9f * dv * a2 + 0.1f * hv0.z,
                                       0.9f * dv * a3 + 0.1f * hv0.w);
            *(float4*)(op + 4) = make_float4(0.9f * dv * a4 + 0.1f * hv1.x,
                                             0.9f * dv * a5 + 0.1f * hv1.y,
                                             0.9f * dv * a6 + 0.1f * hv1.z,
                                             0.9f * dv * a7 + 0.1f * hv1.w);
        }
    }
}

// ---------------- launch ----------------
extern "C" void kernel_launch(void* const* d_in, const int* in_sizes, int n_in,
                              void* d_out, int out_size)
{
    const float* x  = (const float*)d_in[0];
    const int*   ei = (const int*)d_in[1];     // int32 (JAX x64 disabled)
    const float* W1 = (const float*)d_in[2];
    const float* b1 = (const float*)d_in[3];
    const float* W2 = (const float*)d_in[4];
    const float* b2 = (const float*)d_in[5];
    float* out = (float*)d_out;

    static cudaStream_t s2 = nullptr;
    static cudaEvent_t evFork = nullptr, evJoin = nullptr;
    if (s2 == nullptr) {
        cudaStreamCreateWithFlags(&s2, cudaStreamNonBlocking);
        cudaEventCreateWithFlags(&evFork, cudaEventDisableTiming);
        cudaEventCreateWithFlags(&evJoin, cudaEventDisableTiming);
    }

    // fork: graph preprocessing -> CSR by dst, on side stream
    cudaEventRecord(evFork, 0);
    cudaStreamWaitEvent(s2, evFork, 0);
    k_zero_cnt<<<(NN + 255) / 256, 256, 0, s2>>>();
    k_count<<<(NE + 255) / 256, 256, 0, s2>>>(ei);
    k_dinv<<<(NN + 255) / 256, 256, 0, s2>>>();
    k_scan1<<<NBLK_SCAN, 1024, 0, s2>>>();
    k_scan2<<<1, 32, 0, s2>>>();
    k_scan3<<<(NN + 255) / 256, 256, 0, s2>>>();
    k_fill<<<(NE + 255) / 256, 256, 0, s2>>>(ei);
    cudaEventRecord(evJoin, s2);

    // MLP encoder on main stream (independent of CSR build)
    dim3 g1((NN + 127) / 128, HID / 128);
    k_gemm1_tf32<<<g1, 256>>>(x, W1, b1, NN, HID, INC);
    dim3 g2((NN + 127) / 128, 1);
    k_gemm2_tf32<<<g2, 256>>>(W2, b2, NN, OUTC, HID);

    // join: prescale + propagation need both the CSR (dinv) and h0
    cudaStreamWaitEvent(0, evJoin, 0);
    k_prescale<<<(NN * (OUTC / 2) + 255) / 256, 256>>>();

    // 10 propagation iterations (ping-pong fp16; last writes fp32 d_out)
    int pgrid = (NN * 32 + 255) / 256;
    k_prop<<<pgrid, 256>>>(0, 1, out);
    k_prop<<<pgrid, 256>>>(1, 2, out);
    k_prop<<<pgrid, 256>>>(2, 1, out);
    k_prop<<<pgrid, 256>>>(1, 2, out);
    k_prop<<<pgrid, 256>>>(2, 1, out);
    k_prop<<<pgrid, 256>>>(1, 2, out);
    k_prop<<<pgrid, 256>>>(2, 1, out);
    k_prop<<<pgrid, 256>>>(1, 2, out);
    k_prop<<<pgrid, 256>>>(2, 1, out);
    k_prop<<<pgrid, 256>>>(1, 3, out);
    (void)in_sizes; (void)n_in; (void)out_size;
}

// round 17
// speedup vs baseline: 1.2155x; 1.0239x over previous
#include <cuda_runtime.h>
#include <cuda_fp16.h>
#include <cstdint>

// Problem constants (fixed by the dataset)
#define NN        100000
#define NE        3200000
#define INC       512
#define HID       256
#define OUTC      64
#define NBLK_SCAN 98      // ceil(NN / 1024)

// ---------------- scratch (static __device__ — no allocations) ----------------
__device__ float   g_hidden[(size_t)NN * HID];     // 102.4 MB
__device__ float   g_h0[(size_t)NN * OUTC];        // 25.6 MB (fp32 residual, final iter)
__device__ __half2 g_h0r16[(size_t)NN * (OUTC/2)]; // fp16 residual (iters 1-9)
__device__ __half2 g_h016[(size_t)NN * (OUTC/2)];  // prescaled fp16 (dinv*h)
__device__ __half2 g_hA16[(size_t)NN * (OUTC/2)];
__device__ __half2 g_hB16[(size_t)NN * (OUTC/2)];
__device__ int     g_cnt[NN];
__device__ int     g_rowptr[NN + 1];
__device__ int     g_fillpos[NN];
__device__ float   g_dinv[NN];
__device__ int     g_esrc[NE];                     // src only, 12.8 MB
__device__ int     g_bsums[NBLK_SCAN];

// ---------------- graph preprocessing ----------------
__global__ void k_zero_cnt() {
    int i = blockIdx.x * blockDim.x + threadIdx.x;
    if (i < NN) g_cnt[i] = 0;
}

// ei is int32 (JAX default x64-disabled downgrades int64 -> int32)
__global__ void k_count(const int* __restrict__ ei) {
    int e = blockIdx.x * blockDim.x + threadIdx.x;
    if (e < NE) {
        int d = ei[NE + e];
        if (d >= 0 && d < NN) atomicAdd(&g_cnt[d], 1);
    }
}

__global__ void k_dinv() {
    int i = blockIdx.x * blockDim.x + threadIdx.x;
    if (i < NN) g_dinv[i] = rsqrtf((float)(g_cnt[i] + 1)); // +1 self loop
}

__global__ void k_scan1() {
    __shared__ int s[1024];
    int tid = threadIdx.x;
    int i = blockIdx.x * 1024 + tid;
    int v = (i < NN) ? g_cnt[i] : 0;
    s[tid] = v;
    __syncthreads();
    for (int off = 1; off < 1024; off <<= 1) {
        int t = (tid >= off) ? s[tid - off] : 0;
        __syncthreads();
        s[tid] += t;
        __syncthreads();
    }
    if (i < NN) g_rowptr[i] = s[tid];
    if (tid == 1023) g_bsums[blockIdx.x] = s[1023];
}

__global__ void k_scan2() {
    if (threadIdx.x == 0) {
        int run = 0;
        for (int b = 0; b < NBLK_SCAN; b++) { int t = g_bsums[b]; g_bsums[b] = run; run += t; }
    }
}

__global__ void k_scan3() {
    int i = blockIdx.x * blockDim.x + threadIdx.x;
    if (i < NN) {
        int ex = g_rowptr[i] - g_cnt[i] + g_bsums[i >> 10]; // global exclusive
        g_rowptr[i]  = ex;
        g_fillpos[i] = ex;
    }
    if (i == 0) g_rowptr[NN] = NE;
}

__global__ void k_fill(const int* __restrict__ ei) {
    int e = blockIdx.x * blockDim.x + threadIdx.x;
    if (e < NE) {
        int s = ei[e];
        int d = ei[NE + e];
        if (s >= 0 && s < NN && d >= 0 && d < NN) {
            int p = atomicAdd(&g_fillpos[d], 1);
            g_esrc[p] = s;
        }
    }
}

// prescale h0 -> fp16 buffers: g_h016 = dinv*h0, g_h0r16 = h0 (both coalesced)
__global__ void k_prescale() {
    int idx = blockIdx.x * blockDim.x + threadIdx.x;   // over NN*32 half2
    if (idx < NN * (OUTC / 2)) {
        int node = idx >> 5;
        float dv = g_dinv[node];
        float2 f = *(const float2*)(g_h0 + ((size_t)idx << 1));
        g_h016[idx]  = __floats2half2_rn(dv * f.x, dv * f.y);
        g_h0r16[idx] = __floats2half2_rn(f.x, f.y);
    }
}

// ---------------- tf32 helpers ----------------
__device__ __forceinline__ uint32_t f2tf(float f) {
    uint32_t u;
    asm("cvt.rna.tf32.f32 %0, %1;" : "=r"(u) : "f"(f));
    return u;
}

// ---------------- tf32 tensor-core GEMM1: C = relu(A @ B + bias) --------------
// 128x128 tile, BK=16, 8 warps (4m x 2n), warp tile 32x64, mma.m16n8k8 tf32
// Single-sync double buffering: one __syncthreads per K-tile.
__global__ void __launch_bounds__(256) k_gemm1_tf32(
    const float* __restrict__ A, const float* __restrict__ B,
    const float* __restrict__ bias, int M, int N, int K)
{
    float* C = (float*)g_hidden;
    __shared__ uint32_t As[2][128][20];
    __shared__ uint32_t Bs[2][16][136];

    int tid = threadIdx.x;
    int lane = tid & 31, wid = tid >> 5;
    int wm = wid & 3, wn = wid >> 2;
    int g = lane >> 2, t = lane & 3;
    int row0 = blockIdx.x * 128, col0 = blockIdx.y * 128;

    int ar0 = tid >> 2;
    int ac  = (tid & 3) << 2;
    int br0 = tid >> 5;
    int bc  = (tid & 31) << 2;

    const float* Ap0 = A + (size_t)(row0 + ar0) * K + ac;
    const float* Ap1 = A + (size_t)(row0 + ar0 + 64) * K + ac;
    bool aok0 = (row0 + ar0) < M;
    bool aok1 = (row0 + ar0 + 64) < M;
    const float* Bp0 = B + (size_t)br0 * N + col0 + bc;
    const float* Bp1 = B + (size_t)(br0 + 8) * N + col0 + bc;

    float c[2][8][4] = {};

    const float4 fz = make_float4(0.f, 0.f, 0.f, 0.f);
    int nk = K >> 4;

    // prologue: tile 0 -> buf 0
    {
        float4 av0 = aok0 ? *(const float4*)Ap0 : fz;
        float4 av1 = aok1 ? *(const float4*)Ap1 : fz;
        float4 bv0 = *(const float4*)Bp0;
        float4 bv1 = *(const float4*)Bp1;
        *(uint4*)&As[0][ar0][ac]      = make_uint4(f2tf(av0.x), f2tf(av0.y), f2tf(av0.z), f2tf(av0.w));
        *(uint4*)&As[0][ar0 + 64][ac] = make_uint4(f2tf(av1.x), f2tf(av1.y), f2tf(av1.z), f2tf(av1.w));
        *(uint4*)&Bs[0][br0][bc]      = make_uint4(f2tf(bv0.x), f2tf(bv0.y), f2tf(bv0.z), f2tf(bv0.w));
        *(uint4*)&Bs[0][br0 + 8][bc]  = make_uint4(f2tf(bv1.x), f2tf(bv1.y), f2tf(bv1.z), f2tf(bv1.w));
    }
    __syncthreads();

    // stage tile 1 in registers
    float4 av0 = fz, av1 = fz, bv0 = fz, bv1 = fz;
    if (nk > 1) {
        av0 = aok0 ? *(const float4*)(Ap0 + 16) : fz;
        av1 = aok1 ? *(const float4*)(Ap1 + 16) : fz;
        bv0 = *(const float4*)(Bp0 + (size_t)16 * N);
        bv1 = *(const float4*)(Bp1 + (size_t)16 * N);
    }

    for (int kt = 0; kt < nk; kt++) {
        int cur = kt & 1, nxt = cur ^ 1;

        // mma on buf[cur]
#pragma unroll
        for (int ks = 0; ks < 2; ks++) {
            int k = ks << 3;
            uint32_t af[2][4];
#pragma unroll
            for (int mi = 0; mi < 2; mi++) {
                int m0 = wm * 32 + mi * 16;
                af[mi][0] = As[cur][m0 + g][k + t];
                af[mi][1] = As[cur][m0 + g + 8][k + t];
                af[mi][2] = As[cur][m0 + g][k + t + 4];
                af[mi][3] = As[cur][m0 + g + 8][k + t + 4];
            }
            uint32_t bf[8][2];
#pragma unroll
            for (int ni = 0; ni < 8; ni++) {
                int n0 = wn * 64 + ni * 8;
                bf[ni][0] = Bs[cur][k + t][n0 + g];
                bf[ni][1] = Bs[cur][k + t + 4][n0 + g];
            }
#pragma unroll
            for (int mi = 0; mi < 2; mi++)
#pragma unroll
                for (int ni = 0; ni < 8; ni++) {
                    asm volatile(
                        "mma.sync.aligned.m16n8k8.row.col.f32.tf32.tf32.f32 "
                        "{%0,%1,%2,%3}, {%4,%5,%6,%7}, {%8,%9}, {%0,%1,%2,%3};"
                        : "+f"(c[mi][ni][0]), "+f"(c[mi][ni][1]),
                          "+f"(c[mi][ni][2]), "+f"(c[mi][ni][3])
                        : "r"(af[mi][0]), "r"(af[mi][1]), "r"(af[mi][2]), "r"(af[mi][3]),
                          "r"(bf[ni][0]), "r"(bf[ni][1]));
                }
        }

        // store staged tile kt+1 into buf[nxt] (its readers finished at the
        // sync ending iteration kt-1)
        if (kt + 1 < nk) {
            *(uint4*)&As[nxt][ar0][ac]      = make_uint4(f2tf(av0.x), f2tf(av0.y), f2tf(av0.z), f2tf(av0.w));
            *(uint4*)&As[nxt][ar0 + 64][ac] = make_uint4(f2tf(av1.x), f2tf(av1.y), f2tf(av1.z), f2tf(av1.w));
            *(uint4*)&Bs[nxt][br0][bc]      = make_uint4(f2tf(bv0.x), f2tf(bv0.y), f2tf(bv0.z), f2tf(bv0.w));
            *(uint4*)&Bs[nxt][br0 + 8][bc]  = make_uint4(f2tf(bv1.x), f2tf(bv1.y), f2tf(bv1.z), f2tf(bv1.w));
        }
        // issue loads for tile kt+2 (consumed by next iteration's store)
        if (kt + 2 < nk) {
            int ko = (kt + 2) << 4;
            av0 = aok0 ? *(const float4*)(Ap0 + ko) : fz;
            av1 = aok1 ? *(const float4*)(Ap1 + ko) : fz;
            bv0 = *(const float4*)(Bp0 + (size_t)ko * N);
            bv1 = *(const float4*)(Bp1 + (size_t)ko * N);
        }
        __syncthreads();
    }

#pragma unroll
    for (int mi = 0; mi < 2; mi++) {
        int r = row0 + wm * 32 + mi * 16 + g;
#pragma unroll
        for (int ni = 0; ni < 8; ni++) {
            int cn = col0 + wn * 64 + ni * 8 + (t << 1);
            float2 bb = *(const float2*)&bias[cn];
            if (r < M) {
                float2 o;
                o.x = fmaxf(c[mi][ni][0] + bb.x, 0.f);
                o.y = fmaxf(c[mi][ni][1] + bb.y, 0.f);
                *(float2*)&C[(size_t)r * N + cn] = o;
            }
            if (r + 8 < M) {
                float2 o;
                o.x = fmaxf(c[mi][ni][2] + bb.x, 0.f);
                o.y = fmaxf(c[mi][ni][3] + bb.y, 0.f);
                *(float2*)&C[(size_t)(r + 8) * N + cn] = o;
            }
        }
    }
}

// ---------------- tf32 tensor-core GEMM2: g_h0 = g_hidden @ W2 + b2 ------------
// 128x64 tile, BK=16, 8 warps (4m x 2n), warp tile 32x32; single-sync DB
__global__ void __launch_bounds__(256) k_gemm2_tf32(
    const float* __restrict__ B, const float* __restrict__ bias,
    int M, int N, int K)
{
    const float* A = (const float*)g_hidden;
    float* C = (float*)g_h0;
    __shared__ uint32_t As[2][128][20];
    __shared__ uint32_t Bs[2][16][72];

    int tid = threadIdx.x;
    int lane = tid & 31, wid = tid >> 5;
    int wm = wid & 3, wn = wid >> 2;
    int g = lane >> 2, t = lane & 3;
    int row0 = blockIdx.x * 128;

    int ar0 = tid >> 2;
    int ac  = (tid & 3) << 2;
    int br0 = tid >> 4;
    int bc  = (tid & 15) << 2;

    const float* Ap0 = A + (size_t)(row0 + ar0) * K + ac;
    const float* Ap1 = A + (size_t)(row0 + ar0 + 64) * K + ac;
    bool aok0 = (row0 + ar0) < M;
    bool aok1 = (row0 + ar0 + 64) < M;
    const float* Bp = B + (size_t)br0 * N + bc;

    float c[2][4][4] = {};

    const float4 fz = make_float4(0.f, 0.f, 0.f, 0.f);
    int nk = K >> 4;

    // prologue: tile 0 -> buf 0
    {
        float4 av0 = aok0 ? *(const float4*)Ap0 : fz;
        float4 av1 = aok1 ? *(const float4*)Ap1 : fz;
        float4 bv = *(const float4*)Bp;
        *(uint4*)&As[0][ar0][ac]      = make_uint4(f2tf(av0.x), f2tf(av0.y), f2tf(av0.z), f2tf(av0.w));
        *(uint4*)&As[0][ar0 + 64][ac] = make_uint4(f2tf(av1.x), f2tf(av1.y), f2tf(av1.z), f2tf(av1.w));
        *(uint4*)&Bs[0][br0][bc]      = make_uint4(f2tf(bv.x), f2tf(bv.y), f2tf(bv.z), f2tf(bv.w));
    }
    __syncthreads();

    float4 av0 = fz, av1 = fz, bv = fz;
    if (nk > 1) {
        av0 = aok0 ? *(const float4*)(Ap0 + 16) : fz;
        av1 = aok1 ? *(const float4*)(Ap1 + 16) : fz;
        bv = *(const float4*)(Bp + (size_t)16 * N);
    }

    for (int kt = 0; kt < nk; kt++) {
        int cur = kt & 1, nxt = cur ^ 1;

#pragma unroll
        for (int ks = 0; ks < 2; ks++) {
            int k = ks << 3;
            uint32_t af[2][4];
#pragma unroll
            for (int mi = 0; mi < 2; mi++) {
                int m0 = wm * 32 + mi * 16;
                af[mi][0] = As[cur][m0 + g][k + t];
                af[mi][1] = As[cur][m0 + g + 8][k + t];
                af[mi][2] = As[cur][m0 + g][k + t + 4];
                af[mi][3] = As[cur][m0 + g + 8][k + t + 4];
            }
            uint32_t bf[4][2];
#pragma unroll
            for (int ni = 0; ni < 4; ni++) {
                int n0 = wn * 32 + ni * 8;
                bf[ni][0] = Bs[cur][k + t][n0 + g];
                bf[ni][1] = Bs[cur][k + t + 4][n0 + g];
            }
#pragma unroll
            for (int mi = 0; mi < 2; mi++)
#pragma unroll
                for (int ni = 0; ni < 4; ni++) {
                    asm volatile(
                        "mma.sync.aligned.m16n8k8.row.col.f32.tf32.tf32.f32 "
                        "{%0,%1,%2,%3}, {%4,%5,%6,%7}, {%8,%9}, {%0,%1,%2,%3};"
                        : "+f"(c[mi][ni][0]), "+f"(c[mi][ni][1]),
                          "+f"(c[mi][ni][2]), "+f"(c[mi][ni][3])
                        : "r"(af[mi][0]), "r"(af[mi][1]), "r"(af[mi][2]), "r"(af[mi][3]),
                          "r"(bf[ni][0]), "r"(bf[ni][1]));
                }
        }

        if (kt + 1 < nk) {
            *(uint4*)&As[nxt][ar0][ac]      = make_uint4(f2tf(av0.x), f2tf(av0.y), f2tf(av0.z), f2tf(av0.w));
            *(uint4*)&As[nxt][ar0 + 64][ac] = make_uint4(f2tf(av1.x), f2tf(av1.y), f2tf(av1.z), f2tf(av1.w));
            *(uint4*)&Bs[nxt][br0][bc]      = make_uint4(f2tf(bv.x), f2tf(bv.y), f2tf(bv.z), f2tf(bv.w));
        }
        if (kt + 2 < nk) {
            int ko = (kt + 2) << 4;
            av0 = aok0 ? *(const float4*)(Ap0 + ko) : fz;
            av1 = aok1 ? *(const float4*)(Ap1 + ko) : fz;
            bv = *(const float4*)(Bp + (size_t)ko * N);
        }
        __syncthreads();
    }

#pragma unroll
    for (int mi = 0; mi < 2; mi++) {
        int r0 = row0 + wm * 32 + mi * 16 + g;
#pragma unroll
        for (int ni = 0; ni < 4; ni++) {
            int cn = wn * 32 + ni * 8 + (t << 1);
            float2 bb = *(const float2*)&bias[cn];
            if (r0 < M) {
                float2 o;
                o.x = c[mi][ni][0] + bb.x;
                o.y = c[mi][ni][1] + bb.y;
                *(float2*)&C[(size_t)r0 * N + cn] = o;
            }
            if (r0 + 8 < M) {
                float2 o;
                o.x = c[mi][ni][2] + bb.x;
                o.y = c[mi][ni][3] + bb.y;
                *(float2*)&C[(size_t)(r0 + 8) * N + cn] = o;
            }
        }
    }
}

// ---------------- propagation ----------------
// gather buffers hold hs = dinv * h (prescaled). Per node d:
//   agg = dinv_d * ( sum_{in-edges} hs[s] + hs[d] )
//   h_next = 0.9*agg + 0.1*h0;  store dinv_d*h_next (fp16) or h_next (fp32 final)
// warp/node; 8 lanes per edge (LDG.128 = 16B/lane covers the 128B row),
// 4 edges per warp-step; fp32 accumulation; two-level shfl_xor(8,16) merge.
__global__ void __launch_bounds__(256) k_prop(int src_id, int dst_id,
                                              float* __restrict__ ext_out)
{
    const __half2* hin = (src_id == 0) ? (const __half2*)g_h016
                       : (src_id == 1) ? (const __half2*)g_hA16
                                       : (const __half2*)g_hB16;
    __half2* hout16 = (dst_id == 1) ? (__half2*)g_hA16
                    : (dst_id == 2) ? (__half2*)g_hB16
                                    : nullptr;

    int node = (blockIdx.x * blockDim.x + threadIdx.x) >> 5;
    int lane = threadIdx.x & 31;
    if (node >= NN) return;
    int sub = lane >> 3;           // edge slot 0..3
    int c   = lane & 7;            // 16-byte chunk: cols 8c..8c+7
    int beg = g_rowptr[node];
    int end = g_rowptr[node + 1];

    float a0 = 0.f, a1 = 0.f, a2 = 0.f, a3 = 0.f;
    float a4 = 0.f, a5 = 0.f, a6 = 0.f, a7 = 0.f;

    for (int base = beg; base < end; base += 32) {
        int nb = end - base; if (nb > 32) nb = 32;
        int es = 0;
        if (lane < nb) es = g_esrc[base + lane];
#pragma unroll
        for (int j = 0; j < 8; j++) {           // 8 steps x 4 edges
            int e = (j << 2) + sub;
            int s = __shfl_sync(0xffffffffu, es, e);
            if (e < nb) {
                uint4 raw = *(const uint4*)(hin + (size_t)s * (OUTC / 2) + (c << 2));
                float2 f0 = __half22float2(*(__half2*)&raw.x);
                float2 f1 = __half22float2(*(__half2*)&raw.y);
                float2 f2 = __half22float2(*(__half2*)&raw.z);
                float2 f3 = __half22float2(*(__half2*)&raw.w);
                a0 += f0.x; a1 += f0.y; a2 += f1.x; a3 += f1.y;
                a4 += f2.x; a5 += f2.y; a6 += f3.x; a7 += f3.y;
            }
            if ((j << 2) + 4 >= nb) break;
        }
    }
    // merge the four quarter-warp partial sums
    a0 += __shfl_xor_sync(0xffffffffu, a0, 8);
    a1 += __shfl_xor_sync(0xffffffffu, a1, 8);
    a2 += __shfl_xor_sync(0xffffffffu, a2, 8);
    a3 += __shfl_xor_sync(0xffffffffu, a3, 8);
    a4 += __shfl_xor_sync(0xffffffffu, a4, 8);
    a5 += __shfl_xor_sync(0xffffffffu, a5, 8);
    a6 += __shfl_xor_sync(0xffffffffu, a6, 8);
    a7 += __shfl_xor_sync(0xffffffffu, a7, 8);
    a0 += __shfl_xor_sync(0xffffffffu, a0, 16);
    a1 += __shfl_xor_sync(0xffffffffu, a1, 16);
    a2 += __shfl_xor_sync(0xffffffffu, a2, 16);
    a3 += __shfl_xor_sync(0xffffffffu, a3, 16);
    a4 += __shfl_xor_sync(0xffffffffu, a4, 16);
    a5 += __shfl_xor_sync(0xffffffffu, a5, 16);
    a6 += __shfl_xor_sync(0xffffffffu, a6, 16);
    a7 += __shfl_xor_sync(0xffffffffu, a7, 16);

    if (sub == 0) {
        float dv = g_dinv[node];
        // self loop (prescaled row)
        uint4 sraw = *(const uint4*)(hin + (size_t)node * (OUTC / 2) + (c << 2));
        {
            float2 f0 = __half22float2(*(__half2*)&sraw.x);
            float2 f1 = __half22float2(*(__half2*)&sraw.y);
            float2 f2 = __half22float2(*(__half2*)&sraw.z);
            float2 f3 = __half22float2(*(__half2*)&sraw.w);
            a0 += f0.x; a1 += f0.y; a2 += f1.x; a3 += f1.y;
            a4 += f2.x; a5 += f2.y; a6 += f3.x; a7 += f3.y;
        }

        if (hout16) {
            // residual from fp16 h0 copy
            uint4 rraw = *(const uint4*)(g_h0r16 + (size_t)node * (OUTC / 2) + (c << 2));
            float2 r0 = __half22float2(*(__half2*)&rraw.x);
            float2 r1 = __half22float2(*(__half2*)&rraw.y);
            float2 r2 = __half22float2(*(__half2*)&rraw.z);
            float2 r3 = __half22float2(*(__half2*)&rraw.w);
            float o0 = 0.9f * dv * a0 + 0.1f * r0.x;
            float o1 = 0.9f * dv * a1 + 0.1f * r0.y;
            float o2 = 0.9f * dv * a2 + 0.1f * r1.x;
            float o3 = 0.9f * dv * a3 + 0.1f * r1.y;
            float o4 = 0.9f * dv * a4 + 0.1f * r2.x;
            float o5 = 0.9f * dv * a5 + 0.1f * r2.y;
            float o6 = 0.9f * dv * a6 + 0.1f * r3.x;
            float o7 = 0.9f * dv * a7 + 0.1f * r3.y;
            uint4 ow;
            *(__half2*)&ow.x = __floats2half2_rn(dv * o0, dv * o1);
            *(__half2*)&ow.y = __floats2half2_rn(dv * o2, dv * o3);
            *(__half2*)&ow.z = __floats2half2_rn(dv * o4, dv * o5);
            *(__half2*)&ow.w = __floats2half2_rn(dv * o6, dv * o7);
            *(uint4*)(hout16 + (size_t)node * (OUTC / 2) + (c << 2)) = ow;
        } else {
            // final iteration: fp32 residual, fp32 output
            const float* h0p = g_h0 + (size_t)node * OUTC + (c << 3);
            float4 hv0 = *(const float4*)h0p;
            float4 hv1 = *(const float4*)(h0p + 4);
            float* op = ext_out + (size_t)node * OUTC + (c << 3);
            *(float4*)op = make_float4(0.9f * dv * a0 + 0.1f * hv0.x,
                                       0.9f * dv * a1 + 0.1f * hv0.y,
                                       0.9f * dv * a2 + 0.1f * hv0.z,
                                       0.9f * dv * a3 + 0.1f * hv0.w);
            *(float4*)(op + 4) = make_float4(0.9f * dv * a4 + 0.1f * hv1.x,
                                             0.9f * dv * a5 + 0.1f * hv1.y,
                                             0.9f * dv * a6 + 0.1f * hv1.z,
                                             0.9f * dv * a7 + 0.1f * hv1.w);
        }
    }
}

// ---------------- launch ----------------
extern "C" void kernel_launch(void* const* d_in, const int* in_sizes, int n_in,
                              void* d_out, int out_size)
{
    const float* x  = (const float*)d_in[0];
    const int*   ei = (const int*)d_in[1];     // int32 (JAX x64 disabled)
    const float* W1 = (const float*)d_in[2];
    const float* b1 = (const float*)d_in[3];
    const float* W2 = (const float*)d_in[4];
    const float* b2 = (const float*)d_in[5];
    float* out = (float*)d_out;

    static cudaStream_t s2 = nullptr;
    static cudaEvent_t evFork = nullptr, evJoin = nullptr;
    if (s2 == nullptr) {
        cudaStreamCreateWithFlags(&s2, cudaStreamNonBlocking);
        cudaEventCreateWithFlags(&evFork, cudaEventDisableTiming);
        cudaEventCreateWithFlags(&evJoin, cudaEventDisableTiming);
    }

    // fork: graph preprocessing -> CSR by dst, on side stream
    cudaEventRecord(evFork, 0);
    cudaStreamWaitEvent(s2, evFork, 0);
    k_zero_cnt<<<(NN + 255) / 256, 256, 0, s2>>>();
    k_count<<<(NE + 255) / 256, 256, 0, s2>>>(ei);
    k_dinv<<<(NN + 255) / 256, 256, 0, s2>>>();
    k_scan1<<<NBLK_SCAN, 1024, 0, s2>>>();
    k_scan2<<<1, 32, 0, s2>>>();
    k_scan3<<<(NN + 255) / 256, 256, 0, s2>>>();
    k_fill<<<(NE + 255) / 256, 256, 0, s2>>>(ei);
    cudaEventRecord(evJoin, s2);

    // MLP encoder on main stream (independent of CSR build)
    dim3 g1((NN + 127) / 128, HID / 128);
    k_gemm1_tf32<<<g1, 256>>>(x, W1, b1, NN, HID, INC);
    dim3 g2((NN + 127) / 128, 1);
    k_gemm2_tf32<<<g2, 256>>>(W2, b2, NN, OUTC, HID);

    // join: prescale + propagation need both the CSR (dinv) and h0
    cudaStreamWaitEvent(0, evJoin, 0);
    k_prescale<<<(NN * (OUTC / 2) + 255) / 256, 256>>>();

    // 10 propagation iterations (ping-pong fp16; last writes fp32 d_out)
    int pgrid = (NN * 32 + 255) / 256;
    k_prop<<<pgrid, 256>>>(0, 1, out);
    k_prop<<<pgrid, 256>>>(1, 2, out);
    k_prop<<<pgrid, 256>>>(2, 1, out);
    k_prop<<<pgrid, 256>>>(1, 2, out);
    k_prop<<<pgrid, 256>>>(2, 1, out);
    k_prop<<<pgrid, 256>>>(1, 2, out);
    k_prop<<<pgrid, 256>>>(2, 1, out);
    k_prop<<<pgrid, 256>>>(1, 2, out);
    k_prop<<<pgrid, 256>>>(2, 1, out);
    k_prop<<<pgrid, 256>>>(1, 3, out);
    (void)in_sizes; (void)n_in; (void)out_size;
}